// round 1
// baseline (speedup 1.0000x reference)
#include <cuda_runtime.h>

#define Bx   1024
#define Tn   200
#define Dn   64
#define Hn   4
#define HDn  16
#define M0n  256
#define M1n  128
#define M2n  64
#define NBT  204800.0f   // B*T

// ---------------- scratch (static device allocations; no cudaMalloc) ---------
__device__ float g_head_out[(size_t)Bx*Hn*Tn*Dn];   // 210 MB
__device__ float g_u1[(size_t)Bx*Hn*Tn*M1n];        // 420 MB
__device__ float g_u2[(size_t)Bx*Hn*Tn*M2n];        // 210 MB
__device__ float g_sum1[Hn*M1n], g_sq1[Hn*M1n], g_mean1[Hn*M1n], g_istd1[Hn*M1n];
__device__ float g_sum2[Hn*M2n], g_sq2[Hn*M2n], g_mean2[Hn*M2n], g_istd2[Hn*M2n];

// ---------------- K0: zero the stat accumulators -----------------------------
__global__ void k_zero() {
    int i = threadIdx.x;
    if (i < Hn*M1n) { g_sum1[i] = 0.f; g_sq1[i] = 0.f; }
    if (i < Hn*M2n) { g_sum2[i] = 0.f; g_sq2[i] = 0.f; }
}

// ---------------- K1: fused QKV + attention + Wo + LN + FFN ------------------
// one block per (b,h), 256 threads
__global__ __launch_bounds__(256, 1)
void k_attn_ffn(const float* __restrict__ seq, const float* __restrict__ Wqkv,
                const float* __restrict__ Wo,  const float* __restrict__ lng,
                const float* __restrict__ lnb, const float* __restrict__ fw1,
                const float* __restrict__ fb1, const float* __restrict__ fw2,
                const float* __restrict__ fb2) {
    extern __shared__ float sm[];
    float* S    = sm;                // [200][65] seq -> s (in place)
    float* Qs   = S   + 200*65;      // [200][17] q -> ctx (in place)
    float* Ks   = Qs  + 200*17;
    float* Vs   = Ks  + 200*17;
    float* WQ   = Vs  + 200*17;      // [3][16][65]
    float* WOs  = WQ  + 3*16*65;     // [64][17]
    float* F1   = WOs + 64*17;       // [64][65]
    float* F2   = F1  + 64*65;       // [64][65]
    float* H1s  = F2  + 64*65;       // [200][65]
    float* LNG  = H1s + 200*65;      // 64
    float* LNB  = LNG + 64;
    float* B1   = LNB + 64;
    float* B2   = B1  + 64;

    const int bid = blockIdx.x;
    const int b = bid >> 2, h = bid & 3;
    const int tid = threadIdx.x;

    // load sequence tile
    const float* seqb = seq + (size_t)b*Tn*Dn;
    for (int o = tid; o < Tn*Dn; o += 256) {
        int t = o >> 6, d = o & 63;
        S[t*65 + d] = seqb[o];
    }
    // load W_qkv head slices
    for (int o = tid; o < 3*16*64; o += 256) {
        int kind = o >> 10;
        int rem  = o & 1023;
        int i = rem >> 6, d = rem & 63;
        WQ[(kind*16 + i)*65 + d] = Wqkv[(size_t)(kind*64 + h*16 + i)*64 + d];
    }
    // W_o[h]
    for (int o = tid; o < 64*16; o += 256) {
        int D = o >> 4, i = o & 15;
        WOs[D*17 + i] = Wo[(size_t)h*64*16 + D*16 + i];
    }
    // ffn weights
    for (int o = tid; o < 64*64; o += 256) {
        int r = o >> 6, c = o & 63;
        F1[r*65 + c] = fw1[(size_t)h*64*64 + o];
        F2[r*65 + c] = fw2[(size_t)h*64*64 + o];
    }
    if (tid < 64) {
        LNG[tid] = lng[h*64 + tid];
        LNB[tid] = lnb[h*64 + tid];
        B1[tid]  = fb1[h*64 + tid];
        B2[tid]  = fb2[h*64 + tid];
    }
    __syncthreads();

    // QKV projection (q pre-scaled by 1/sqrt(HD) = 0.25)
    for (int o = tid; o < 3*Tn*16; o += 256) {
        int kind = o / 3200;
        int rem  = o - kind*3200;
        int t = rem >> 4, i = rem & 15;
        const float* wr = &WQ[(kind*16 + i)*65];
        const float* sr = &S[t*65];
        float a0=0.f, a1=0.f, a2=0.f, a3=0.f;
        #pragma unroll
        for (int d = 0; d < 64; d += 4) {
            a0 += sr[d]   * wr[d];
            a1 += sr[d+1] * wr[d+1];
            a2 += sr[d+2] * wr[d+2];
            a3 += sr[d+3] * wr[d+3];
        }
        float acc = (a0+a1) + (a2+a3);
        if (kind == 0)      Qs[t*17 + i] = acc * 0.25f;
        else if (kind == 1) Ks[t*17 + i] = acc;
        else                Vs[t*17 + i] = acc;
    }
    __syncthreads();

    // attention: warp wp handles rows [wp*25, wp*25+25)
    const int lane = tid & 31, wp = tid >> 5;
    for (int r = 0; r < 25; r++) {
        int t = wp*25 + r;
        float q[16];
        #pragma unroll
        for (int i = 0; i < 16; i++) q[i] = Qs[t*17 + i];
        float sc[7];
        float mx = -1e30f;
        #pragma unroll
        for (int m = 0; m < 7; m++) {
            int j = lane + 32*m;
            float v = -1e30f;
            if (j < Tn) {
                float b0=0.f, b1v=0.f;
                #pragma unroll
                for (int i = 0; i < 16; i += 2) {
                    b0  += q[i]   * Ks[j*17 + i];
                    b1v += q[i+1] * Ks[j*17 + i + 1];
                }
                v = b0 + b1v;
            }
            sc[m] = v;
            mx = fmaxf(mx, v);
        }
        #pragma unroll
        for (int off = 16; off >= 1; off >>= 1)
            mx = fmaxf(mx, __shfl_xor_sync(0xffffffffu, mx, off));
        float lsum = 0.f;
        #pragma unroll
        for (int m = 0; m < 7; m++) {
            int j = lane + 32*m;
            float p = (j < Tn) ? __expf(sc[m] - mx) : 0.f;
            sc[m] = p;
            lsum += p;
        }
        #pragma unroll
        for (int off = 16; off >= 1; off >>= 1)
            lsum += __shfl_xor_sync(0xffffffffu, lsum, off);
        float inv = 1.f / lsum;
        float acc[16];
        #pragma unroll
        for (int i = 0; i < 16; i++) acc[i] = 0.f;
        #pragma unroll
        for (int m = 0; m < 7; m++) {
            int j = lane + 32*m;
            if (j < Tn) {
                float p = sc[m];
                #pragma unroll
                for (int i = 0; i < 16; i++) acc[i] += p * Vs[j*17 + i];
            }
        }
        #pragma unroll
        for (int i = 0; i < 16; i++) {
            float v = acc[i];
            #pragma unroll
            for (int off = 16; off >= 1; off >>= 1)
                v += __shfl_xor_sync(0xffffffffu, v, off);
            if (lane == 0) Qs[t*17 + i] = v * inv;   // ctx overwrites q (row-private)
        }
    }
    __syncthreads();

    // s = ctx @ Wo^T + seq  (in place into S)
    for (int o = tid; o < Tn*Dn; o += 256) {
        int t = o >> 6, D = o & 63;
        float a0=0.f, a1=0.f;
        #pragma unroll
        for (int i = 0; i < 16; i += 2) {
            a0 += Qs[t*17 + i]     * WOs[D*17 + i];
            a1 += Qs[t*17 + i + 1] * WOs[D*17 + i + 1];
        }
        S[t*65 + D] += a0 + a1;
    }
    __syncthreads();

    // LayerNorm per row (warp per row)
    for (int r = 0; r < 25; r++) {
        int t = wp*25 + r;
        float x0 = S[t*65 + lane], x1 = S[t*65 + lane + 32];
        float s1 = x0 + x1, s2 = x0*x0 + x1*x1;
        #pragma unroll
        for (int off = 16; off >= 1; off >>= 1) {
            s1 += __shfl_xor_sync(0xffffffffu, s1, off);
            s2 += __shfl_xor_sync(0xffffffffu, s2, off);
        }
        float mu  = s1 * (1.f/64.f);
        float var = s2 * (1.f/64.f) - mu*mu;
        float rstd = rsqrtf(var + 1e-5f);
        S[t*65 + lane]      = (x0 - mu)*rstd*LNG[lane]      + LNB[lane];
        S[t*65 + lane + 32] = (x1 - mu)*rstd*LNG[lane + 32] + LNB[lane + 32];
    }
    __syncthreads();

    // FFN layer 1 (relu)
    for (int o = tid; o < Tn*64; o += 256) {
        int t = o >> 6, f = o & 63;
        float a0=B1[f], a1=0.f, a2=0.f, a3=0.f;
        #pragma unroll
        for (int d = 0; d < 64; d += 4) {
            a0 += S[t*65 + d]   * F1[f*65 + d];
            a1 += S[t*65 + d+1] * F1[f*65 + d+1];
            a2 += S[t*65 + d+2] * F1[f*65 + d+2];
            a3 += S[t*65 + d+3] * F1[f*65 + d+3];
        }
        H1s[t*65 + f] = fmaxf((a0+a1)+(a2+a3), 0.f);
    }
    __syncthreads();

    // FFN layer 2 + residual -> head_out (gmem)
    float* hob = g_head_out + (size_t)bid*Tn*Dn;
    for (int o = tid; o < Tn*64; o += 256) {
        int t = o >> 6, D = o & 63;
        float a0 = B2[D] + S[t*65 + D], a1=0.f, a2=0.f, a3=0.f;
        #pragma unroll
        for (int f = 0; f < 64; f += 4) {
            a0 += H1s[t*65 + f]   * F2[D*65 + f];
            a1 += H1s[t*65 + f+1] * F2[D*65 + f+1];
            a2 += H1s[t*65 + f+2] * F2[D*65 + f+2];
            a3 += H1s[t*65 + f+3] * F2[D*65 + f+3];
        }
        hob[o] = (a0+a1) + (a2+a3);
    }
}

// ---------------- K2: DIN MLP1 via effective-weight trick --------------------
// u1[t,f] = c0[f] + sum_d ho[t,d]*wB[f,d]  (64-wide instead of 256-wide GEMM)
__global__ __launch_bounds__(256)
void k_din1(const float* __restrict__ te_g, const float* __restrict__ mw1,
            const float* __restrict__ mb1) {
    extern __shared__ float sm[];
    float* HO = sm;                // [200][65]
    float* WB = HO + 200*65;       // [128][65]
    float* C0 = WB + 128*65;       // 128
    float* TE = C0 + 128;          // 64
    float* SS = TE + 64;           // 128
    float* SQ = SS + 128;          // 128

    const int bid = blockIdx.x;
    const int b = bid >> 2, h = bid & 3;
    const int tid = threadIdx.x;

    if (tid < 64)  TE[tid] = te_g[b*64 + tid];
    if (tid < 128) { SS[tid] = 0.f; SQ[tid] = 0.f; }
    const float* hob = g_head_out + (size_t)bid*Tn*Dn;
    for (int o = tid; o < Tn*Dn; o += 256)
        HO[(o >> 6)*65 + (o & 63)] = hob[o];
    __syncthreads();

    const float* W = mw1 + (size_t)h*M1n*M0n;
    for (int o = tid; o < 128*64; o += 256) {
        int f = o >> 6, d = o & 63;
        const float* wr = W + (size_t)f*256;
        WB[f*65 + d] = wr[64 + d] - wr[128 + d] + TE[d]*wr[192 + d];
    }
    if (tid < 128) {
        const float* wr = W + (size_t)tid*256;
        float c = mb1[h*128 + tid];
        for (int d = 0; d < 64; d++) c += TE[d]*(wr[d] + wr[128 + d]);
        C0[tid] = c;
    }
    __syncthreads();

    const int tx = tid & 31, ty = tid >> 5;
    float* u1b = g_u1 + (size_t)bid*Tn*M1n;
    float sacc[4] = {0,0,0,0}, sqacc[4] = {0,0,0,0};

    for (int t0 = 0; t0 < Tn; t0 += 32) {
        int tb = t0 + ty*4;
        float acc[4][4];
        #pragma unroll
        for (int j = 0; j < 4; j++)
            #pragma unroll
            for (int i = 0; i < 4; i++) acc[j][i] = 0.f;
        #pragma unroll 4
        for (int d = 0; d < 64; d++) {
            float hv[4];
            #pragma unroll
            for (int j = 0; j < 4; j++) {
                int t = tb + j; if (t > 199) t = 199;
                hv[j] = HO[t*65 + d];
            }
            float wv[4];
            #pragma unroll
            for (int i = 0; i < 4; i++) wv[i] = WB[(tx + 32*i)*65 + d];
            #pragma unroll
            for (int j = 0; j < 4; j++)
                #pragma unroll
                for (int i = 0; i < 4; i++) acc[j][i] += hv[j]*wv[i];
        }
        #pragma unroll
        for (int j = 0; j < 4; j++) {
            int t = tb + j;
            if (t < Tn) {
                #pragma unroll
                for (int i = 0; i < 4; i++) {
                    int f = tx + 32*i;
                    float u = acc[j][i] + C0[f];
                    u1b[t*128 + f] = u;
                    sacc[i]  += u;
                    sqacc[i] += u*u;
                }
            }
        }
    }
    #pragma unroll
    for (int i = 0; i < 4; i++) {
        atomicAdd(&SS[tx + 32*i], sacc[i]);
        atomicAdd(&SQ[tx + 32*i], sqacc[i]);
    }
    __syncthreads();
    if (tid < 128) {
        atomicAdd(&g_sum1[h*128 + tid], SS[tid]);
        atomicAdd(&g_sq1[h*128 + tid],  SQ[tid]);
    }
}

__global__ void k_fin1() {
    int i = threadIdx.x + blockIdx.x*blockDim.x;
    if (i < Hn*M1n) {
        float invN = 1.f / NBT;
        float m = g_sum1[i] * invN;
        float v = g_sq1[i] * invN - m*m;
        g_mean1[i] = m;
        g_istd1[i] = rsqrtf(v + 1e-9f);
    }
}

// ---------------- K3: dice(u1) @ mw2^T + mb2 -> u2, stats2 -------------------
__global__ __launch_bounds__(256)
void k_din2(const float* __restrict__ mw2, const float* __restrict__ mb2,
            const float* __restrict__ alpha1) {
    extern __shared__ float sm[];
    float* X1 = sm;                 // [200][129]
    float* W2 = X1 + 200*129;       // [64][129]
    float* MN = W2 + 64*129;        // 128
    float* IS = MN + 128;
    float* AL = IS + 128;
    float* C0 = AL + 128;           // 64
    float* SS = C0 + 64;            // 64
    float* SQ = SS + 64;            // 64

    const int bid = blockIdx.x;
    const int h = bid & 3;
    const int tid = threadIdx.x;

    if (tid < 128) {
        MN[tid] = g_mean1[h*128 + tid];
        IS[tid] = g_istd1[h*128 + tid];
        AL[tid] = alpha1[h*128 + tid];
    }
    if (tid < 64) { C0[tid] = mb2[h*64 + tid]; SS[tid] = 0.f; SQ[tid] = 0.f; }
    for (int o = tid; o < 64*128; o += 256) {
        int g = o >> 7, d = o & 127;
        W2[g*129 + d] = mw2[(size_t)h*64*128 + o];
    }
    __syncthreads();

    const float* u1b = g_u1 + (size_t)bid*Tn*M1n;
    for (int o = tid; o < Tn*M1n; o += 256) {
        int t = o >> 7, f = o & 127;
        float x = u1b[o];
        float z = (x - MN[f]) * IS[f];
        float p = 1.f / (1.f + __expf(-z));
        X1[t*129 + f] = (p + AL[f]*(1.f - p)) * x;
    }
    __syncthreads();

    const int tx = tid & 31, ty = tid >> 5;
    float* u2b = g_u2 + (size_t)bid*Tn*M2n;
    float sacc[2] = {0,0}, sqacc[2] = {0,0};

    for (int t0 = 0; t0 < Tn; t0 += 32) {
        int tb = t0 + ty*4;
        float acc[4][2];
        #pragma unroll
        for (int j = 0; j < 4; j++) { acc[j][0] = 0.f; acc[j][1] = 0.f; }
        #pragma unroll 4
        for (int d = 0; d < 128; d++) {
            float hv[4];
            #pragma unroll
            for (int j = 0; j < 4; j++) {
                int t = tb + j; if (t > 199) t = 199;
                hv[j] = X1[t*129 + d];
            }
            float w0 = W2[tx*129 + d];
            float w1 = W2[(tx + 32)*129 + d];
            #pragma unroll
            for (int j = 0; j < 4; j++) {
                acc[j][0] += hv[j]*w0;
                acc[j][1] += hv[j]*w1;
            }
        }
        #pragma unroll
        for (int j = 0; j < 4; j++) {
            int t = tb + j;
            if (t < Tn) {
                #pragma unroll
                for (int i = 0; i < 2; i++) {
                    int g = tx + 32*i;
                    float u = acc[j][i] + C0[g];
                    u2b[t*64 + g] = u;
                    sacc[i]  += u;
                    sqacc[i] += u*u;
                }
            }
        }
    }
    #pragma unroll
    for (int i = 0; i < 2; i++) {
        atomicAdd(&SS[tx + 32*i], sacc[i]);
        atomicAdd(&SQ[tx + 32*i], sqacc[i]);
    }
    __syncthreads();
    if (tid < 64) {
        atomicAdd(&g_sum2[h*64 + tid], SS[tid]);
        atomicAdd(&g_sq2[h*64 + tid],  SQ[tid]);
    }
}

__global__ void k_fin2() {
    int i = threadIdx.x + blockIdx.x*blockDim.x;
    if (i < Hn*M2n) {
        float invN = 1.f / NBT;
        float m = g_sum2[i] * invN;
        float v = g_sq2[i] * invN - m*m;
        g_mean2[i] = m;
        g_istd2[i] = rsqrtf(v + 1e-9f);
    }
}

// ---------------- K4: dice(u2) -> score -> masked softmax -> interests -------
__global__ __launch_bounds__(256)
void k_final(const int* __restrict__ pad, const float* __restrict__ alpha2,
             const float* __restrict__ mw3, const float* __restrict__ mb3,
             float* __restrict__ out) {
    extern __shared__ float sm[];
    float* U2 = sm;                 // [200][65]
    float* HO = U2 + 200*65;        // [200][65]
    float* SC = HO + 200*65;        // 256
    float* RD = SC + 256;           // 256
    float* MN = RD + 256;           // 64
    float* IS = MN + 64;
    float* AL = IS + 64;
    float* W3 = AL + 64;
    float* PT = W3 + 64;            // 256 partials

    const int bid = blockIdx.x;
    const int b = bid >> 2, h = bid & 3;
    const int tid = threadIdx.x;

    if (tid < 64) {
        MN[tid] = g_mean2[h*64 + tid];
        IS[tid] = g_istd2[h*64 + tid];
        AL[tid] = alpha2[h*64 + tid];
        W3[tid] = mw3[h*64 + tid];
    }
    const float* u2b = g_u2 + (size_t)bid*Tn*M2n;
    const float* hob = g_head_out + (size_t)bid*Tn*Dn;
    for (int o = tid; o < Tn*64; o += 256) {
        int t = o >> 6, d = o & 63;
        U2[t*65 + d] = u2b[o];
        HO[t*65 + d] = hob[o];
    }
    __syncthreads();

    float b3 = mb3[h];
    float v = -1e30f;
    if (tid < Tn) {
        float s = b3;
        #pragma unroll 4
        for (int f = 0; f < 64; f++) {
            float x = U2[tid*65 + f];
            float z = (x - MN[f]) * IS[f];
            float p = 1.f / (1.f + __expf(-z));
            s += (p + AL[f]*(1.f - p)) * x * W3[f];
        }
        if (pad[b*Tn + tid] == 0) s = -1e9f;
        v = s;
    }
    SC[tid] = v;
    RD[tid] = v;
    __syncthreads();
    for (int s2 = 128; s2 >= 1; s2 >>= 1) {
        if (tid < s2) RD[tid] = fmaxf(RD[tid], RD[tid + s2]);
        __syncthreads();
    }
    float mx = RD[0];
    __syncthreads();
    float p = (tid < Tn) ? __expf(SC[tid] - mx) : 0.f;
    SC[tid] = p;
    RD[tid] = p;
    __syncthreads();
    for (int s2 = 128; s2 >= 1; s2 >>= 1) {
        if (tid < s2) RD[tid] += RD[tid + s2];
        __syncthreads();
    }
    float inv = 1.f / RD[0];

    // interests: 4 segments of 50 timesteps per output dim
    const int d = tid & 63, seg = tid >> 6;
    float acc = 0.f;
    #pragma unroll 2
    for (int t = seg*50; t < seg*50 + 50; t++)
        acc += SC[t] * HO[t*65 + d];
    PT[seg*64 + d] = acc;
    __syncthreads();
    if (tid < 64) {
        float r = (PT[tid] + PT[64 + tid] + PT[128 + tid] + PT[192 + tid]) * inv;
        out[(size_t)bid*64 + tid] = r;
    }
}

// ---------------- launch -----------------------------------------------------
extern "C" void kernel_launch(void* const* d_in, const int* in_sizes, int n_in,
                              void* d_out, int out_size) {
    const float* seq  = (const float*)d_in[0];
    const float* te   = (const float*)d_in[1];
    const int*   pad  = (const int*)  d_in[2];
    const float* Wqkv = (const float*)d_in[3];
    const float* Wo   = (const float*)d_in[4];
    const float* lng  = (const float*)d_in[5];
    const float* lnb  = (const float*)d_in[6];
    const float* fw1  = (const float*)d_in[7];
    const float* fb1  = (const float*)d_in[8];
    const float* fw2  = (const float*)d_in[9];
    const float* fb2  = (const float*)d_in[10];
    const float* mw1  = (const float*)d_in[11];
    const float* mb1  = (const float*)d_in[12];
    const float* al1  = (const float*)d_in[13];
    const float* mw2  = (const float*)d_in[14];
    const float* mb2  = (const float*)d_in[15];
    const float* al2  = (const float*)d_in[16];
    const float* mw3  = (const float*)d_in[17];
    const float* mb3  = (const float*)d_in[18];
    float* out = (float*)d_out;

    const size_t sm1 = (size_t)(200*65 + 3*200*17 + 3*16*65 + 64*17
                                + 2*64*65 + 200*65 + 4*64) * sizeof(float);
    const size_t sm2 = (size_t)(200*65 + 128*65 + 128 + 64 + 256) * sizeof(float);
    const size_t sm3 = (size_t)(200*129 + 64*129 + 3*128 + 3*64) * sizeof(float);
    const size_t sm4 = (size_t)(2*200*65 + 2*256 + 4*64 + 256) * sizeof(float);

    cudaFuncSetAttribute(k_attn_ffn, cudaFuncAttributeMaxDynamicSharedMemorySize, (int)sm1);
    cudaFuncSetAttribute(k_din1,     cudaFuncAttributeMaxDynamicSharedMemorySize, (int)sm2);
    cudaFuncSetAttribute(k_din2,     cudaFuncAttributeMaxDynamicSharedMemorySize, (int)sm3);
    cudaFuncSetAttribute(k_final,    cudaFuncAttributeMaxDynamicSharedMemorySize, (int)sm4);

    const int grid = Bx * Hn;

    k_zero<<<1, 512>>>();
    k_attn_ffn<<<grid, 256, sm1>>>(seq, Wqkv, Wo, lng, lnb, fw1, fb1, fw2, fb2);
    k_din1<<<grid, 256, sm2>>>(te, mw1, mb1);
    k_fin1<<<1, 512>>>();
    k_din2<<<grid, 256, sm3>>>(mw2, mb2, al1);
    k_fin2<<<1, 256>>>();
    k_final<<<grid, 256, sm4>>>(pad, al2, mw3, mb3, out);
}

// round 7
// speedup vs baseline: 1.9721x; 1.9721x over previous
#include <cuda_runtime.h>

#define Bx   1024
#define Tn   200
#define Hn   4
#define NBT  204800.0f
#define ST   212      // d-major activation row stride (mult of 4)
#define XT   204      // K3 d-major stride

__device__ float g_head_out[(size_t)Bx*Hn*Tn*64];
__device__ float g_u1[(size_t)Bx*Hn*Tn*128];
__device__ float g_u2[(size_t)Bx*Hn*Tn*64];
__device__ float g_sum1[512], g_sq1[512], g_mean1[512], g_istd1[512];
__device__ float g_sum2[256], g_sq2[256], g_mean2[256], g_istd2[256];

__device__ __forceinline__ float4 f4fma(float4 a, float4 h, float s) {
    a.x = fmaf(h.x, s, a.x); a.y = fmaf(h.y, s, a.y);
    a.z = fmaf(h.z, s, a.z); a.w = fmaf(h.w, s, a.w);
    return a;
}

__global__ void k_zero() {
    int i = threadIdx.x;
    if (i < 512) { g_sum1[i] = 0.f; g_sq1[i] = 0.f; }
    if (i < 256) { g_sum2[i] = 0.f; g_sq2[i] = 0.f; }
}

// ---------------- K1: fused QKV + attention + Wo + LN + FFN ------------------
__global__ __launch_bounds__(512, 1)
void k_attn_ffn(const float* __restrict__ seq, const float* __restrict__ Wqkv,
                const float* __restrict__ Wo,  const float* __restrict__ lng,
                const float* __restrict__ lnb, const float* __restrict__ fw1,
                const float* __restrict__ fb1, const float* __restrict__ fw2,
                const float* __restrict__ fb2) {
    extern __shared__ float sm[];
    float* Sd  = sm;             // [64][ST]  seq -> s (d-major)
    float* H1d = Sd  + 64*ST;    // [64][ST]  h1 (f-major)
    float* Qd  = H1d + 64*ST;    // [16][ST]
    float* Kd  = Qd  + 16*ST;
    float* Cd  = Kd  + 16*ST;    // ctx (i-major)
    float* Vs  = Cd  + 16*ST;    // [200][17]
    float* WQd = Vs  + 200*17;   // [64][52]  d-major, col e = kind*16+i
    float* WOd = WQd + 64*52;    // [16][68]  i-major
    float* F1d = WOd + 16*68;    // [64][68]  d-major
    float* F2d = F1d + 64*68;    // [64][68]  f-major
    float* CN  = F2d + 64*68;    // 256: lng,lnb,b1,b2

    const int bid = blockIdx.x, b = bid >> 2, h = bid & 3;
    const int tid = threadIdx.x;

    const float* seqb = seq + (size_t)b*Tn*64;
    for (int o = tid; o < Tn*64; o += 512)
        Sd[(o & 63)*ST + (o >> 6)] = seqb[o];
    for (int o = tid; o < 48*64; o += 512) {
        int e = o >> 6, d = o & 63;
        int kind = e >> 4, i = e & 15;
        WQd[d*52 + e] = Wqkv[(size_t)(kind*64 + h*16 + i)*64 + d];
    }
    for (int o = tid; o < 1024; o += 512) {
        int D = o >> 4, i = o & 15;
        WOd[i*68 + D] = Wo[h*1024 + o];
    }
    for (int o = tid; o < 4096; o += 512) {
        int r = o >> 6, c = o & 63;
        F1d[c*68 + r] = fw1[h*4096 + o];   // [d][f]
        F2d[c*68 + r] = fw2[h*4096 + o];   // [f][D]
    }
    if (tid < 64) {
        CN[tid]       = lng[h*64 + tid];
        CN[64 + tid]  = lnb[h*64 + tid];
        CN[128 + tid] = fb1[h*64 + tid];
        CN[192 + tid] = fb2[h*64 + tid];
    }
    __syncthreads();

    // ---- QKV projection (q pre-scaled by 0.25) ----
    for (int tile = tid; tile < 600; tile += 512) {
        int te = tile % 12, tt = tile / 12;
        int t0 = tt*4, e0 = te*4;
        float4 c0 = {0,0,0,0}, c1 = c0, c2 = c0, c3 = c0;
        #pragma unroll 4
        for (int d = 0; d < 64; d++) {
            float4 hv = *(const float4*)(Sd + d*ST + t0);
            float4 wv = *(const float4*)(WQd + d*52 + e0);
            c0 = f4fma(c0, hv, wv.x); c1 = f4fma(c1, hv, wv.y);
            c2 = f4fma(c2, hv, wv.z); c3 = f4fma(c3, hv, wv.w);
        }
        if (e0 < 16) {
            c0.x*=0.25f;c0.y*=0.25f;c0.z*=0.25f;c0.w*=0.25f;
            c1.x*=0.25f;c1.y*=0.25f;c1.z*=0.25f;c1.w*=0.25f;
            c2.x*=0.25f;c2.y*=0.25f;c2.z*=0.25f;c2.w*=0.25f;
            c3.x*=0.25f;c3.y*=0.25f;c3.z*=0.25f;c3.w*=0.25f;
            *(float4*)(Qd + (e0+0)*ST + t0) = c0;
            *(float4*)(Qd + (e0+1)*ST + t0) = c1;
            *(float4*)(Qd + (e0+2)*ST + t0) = c2;
            *(float4*)(Qd + (e0+3)*ST + t0) = c3;
        } else if (e0 < 32) {
            int e = e0 - 16;
            *(float4*)(Kd + (e+0)*ST + t0) = c0;
            *(float4*)(Kd + (e+1)*ST + t0) = c1;
            *(float4*)(Kd + (e+2)*ST + t0) = c2;
            *(float4*)(Kd + (e+3)*ST + t0) = c3;
        } else {
            int vc = e0 - 32;
            Vs[(t0+0)*17+vc+0]=c0.x; Vs[(t0+1)*17+vc+0]=c0.y; Vs[(t0+2)*17+vc+0]=c0.z; Vs[(t0+3)*17+vc+0]=c0.w;
            Vs[(t0+0)*17+vc+1]=c1.x; Vs[(t0+1)*17+vc+1]=c1.y; Vs[(t0+2)*17+vc+1]=c1.z; Vs[(t0+3)*17+vc+1]=c1.w;
            Vs[(t0+0)*17+vc+2]=c2.x; Vs[(t0+1)*17+vc+2]=c2.y; Vs[(t0+2)*17+vc+2]=c2.z; Vs[(t0+3)*17+vc+2]=c2.w;
            Vs[(t0+0)*17+vc+3]=c3.x; Vs[(t0+1)*17+vc+3]=c3.y; Vs[(t0+2)*17+vc+3]=c3.z; Vs[(t0+3)*17+vc+3]=c3.w;
        }
    }
    __syncthreads();

    // ---- attention: 2 rows per warp pass ----
    const int lane = tid & 31, wp = tid >> 5;
    for (int p = wp; p < 100; p += 16) {
        int r0 = 2*p, r1 = r0 + 1;
        float q0[16], q1[16];
        #pragma unroll
        for (int i = 0; i < 16; i++) {
            q0[i] = Qd[i*ST + r0];
            q1[i] = Qd[i*ST + r1];
        }
        float s0[7], s1[7], m0 = -1e30f, m1 = -1e30f;
        #pragma unroll
        for (int m = 0; m < 7; m++) {
            int j = lane + 32*m;
            float x0 = -1e30f, x1 = -1e30f;
            if (j < 200) {
                float a0 = 0.f, a1 = 0.f;
                #pragma unroll
                for (int i = 0; i < 16; i++) {
                    float kv = Kd[i*ST + j];
                    a0 = fmaf(q0[i], kv, a0);
                    a1 = fmaf(q1[i], kv, a1);
                }
                x0 = a0; x1 = a1;
            }
            s0[m] = x0; s1[m] = x1;
            m0 = fmaxf(m0, x0); m1 = fmaxf(m1, x1);
        }
        #pragma unroll
        for (int off = 16; off >= 1; off >>= 1) {
            m0 = fmaxf(m0, __shfl_xor_sync(0xffffffffu, m0, off));
            m1 = fmaxf(m1, __shfl_xor_sync(0xffffffffu, m1, off));
        }
        float l0 = 0.f, l1 = 0.f;
        #pragma unroll
        for (int m = 0; m < 7; m++) {
            int j = lane + 32*m;
            float p0 = 0.f, p1 = 0.f;
            if (j < 200) { p0 = __expf(s0[m]-m0); p1 = __expf(s1[m]-m1); }
            s0[m] = p0; s1[m] = p1;
            l0 += p0; l1 += p1;
        }
        #pragma unroll
        for (int off = 16; off >= 1; off >>= 1) {
            l0 += __shfl_xor_sync(0xffffffffu, l0, off);
            l1 += __shfl_xor_sync(0xffffffffu, l1, off);
        }
        float inv0 = 1.f/l0, inv1 = 1.f/l1;

        float v[32];
        #pragma unroll
        for (int k = 0; k < 32; k++) v[k] = 0.f;
        #pragma unroll
        for (int m = 0; m < 7; m++) {
            int j = lane + 32*m;
            if (j < 200) {
                float p0 = s0[m], p1 = s1[m];
                #pragma unroll
                for (int i = 0; i < 16; i++) {
                    float vv = Vs[j*17 + i];
                    v[i]    = fmaf(p0, vv, v[i]);
                    v[16+i] = fmaf(p1, vv, v[16+i]);
                }
            }
        }
        // array-halving butterfly: lane j ends with sum of element j in v[0]
        #pragma unroll
        for (int w = 16; w >= 1; w >>= 1) {
            #pragma unroll
            for (int k = 0; k < 16; k++) {
                if (k < w) {
                    float send = (lane & w) ? v[k] : v[k + w];
                    float other = __shfl_xor_sync(0xffffffffu, send, w);
                    v[k] = ((lane & w) ? v[k + w] : v[k]) + other;
                }
            }
        }
        if (lane < 16) Cd[lane*ST + r0]      = v[0] * inv0;
        else           Cd[(lane-16)*ST + r1] = v[0] * inv1;
    }
    __syncthreads();

    // ---- s = ctx @ Wo^T + seq (in place in Sd) ----
    for (int tile = tid; tile < 800; tile += 512) {
        int t0 = (tile >> 4)*4, D0 = (tile & 15)*4;
        float4 c0 = *(const float4*)(Sd + (D0+0)*ST + t0);
        float4 c1 = *(const float4*)(Sd + (D0+1)*ST + t0);
        float4 c2 = *(const float4*)(Sd + (D0+2)*ST + t0);
        float4 c3 = *(const float4*)(Sd + (D0+3)*ST + t0);
        #pragma unroll
        for (int i = 0; i < 16; i++) {
            float4 hv = *(const float4*)(Cd + i*ST + t0);
            float4 wv = *(const float4*)(WOd + i*68 + D0);
            c0 = f4fma(c0, hv, wv.x); c1 = f4fma(c1, hv, wv.y);
            c2 = f4fma(c2, hv, wv.z); c3 = f4fma(c3, hv, wv.w);
        }
        *(float4*)(Sd + (D0+0)*ST + t0) = c0;
        *(float4*)(Sd + (D0+1)*ST + t0) = c1;
        *(float4*)(Sd + (D0+2)*ST + t0) = c2;
        *(float4*)(Sd + (D0+3)*ST + t0) = c3;
    }
    __syncthreads();

    // ---- LayerNorm over d, one thread per row t ----
    if (tid < 200) {
        int t = tid;
        float s1 = 0.f, s2 = 0.f;
        #pragma unroll 8
        for (int d = 0; d < 64; d++) {
            float x = Sd[d*ST + t];
            s1 += x; s2 = fmaf(x, x, s2);
        }
        float mu = s1 * (1.f/64.f);
        float var = s2 * (1.f/64.f) - mu*mu;
        float rs = rsqrtf(var + 1e-5f);
        #pragma unroll 8
        for (int d = 0; d < 64; d++) {
            float x = Sd[d*ST + t];
            Sd[d*ST + t] = (x - mu)*rs*CN[d] + CN[64 + d];
        }
    }
    __syncthreads();

    // ---- FFN1 (relu) -> H1d ----
    for (int tile = tid; tile < 800; tile += 512) {
        int t0 = (tile >> 4)*4, f0 = (tile & 15)*4;
        float b0=CN[128+f0], b1=CN[128+f0+1], b2=CN[128+f0+2], b3=CN[128+f0+3];
        float4 c0 = {b0,b0,b0,b0}, c1 = {b1,b1,b1,b1}, c2 = {b2,b2,b2,b2}, c3 = {b3,b3,b3,b3};
        #pragma unroll 4
        for (int d = 0; d < 64; d++) {
            float4 hv = *(const float4*)(Sd + d*ST + t0);
            float4 wv = *(const float4*)(F1d + d*68 + f0);
            c0 = f4fma(c0, hv, wv.x); c1 = f4fma(c1, hv, wv.y);
            c2 = f4fma(c2, hv, wv.z); c3 = f4fma(c3, hv, wv.w);
        }
        c0.x=fmaxf(c0.x,0.f); c0.y=fmaxf(c0.y,0.f); c0.z=fmaxf(c0.z,0.f); c0.w=fmaxf(c0.w,0.f);
        c1.x=fmaxf(c1.x,0.f); c1.y=fmaxf(c1.y,0.f); c1.z=fmaxf(c1.z,0.f); c1.w=fmaxf(c1.w,0.f);
        c2.x=fmaxf(c2.x,0.f); c2.y=fmaxf(c2.y,0.f); c2.z=fmaxf(c2.z,0.f); c2.w=fmaxf(c2.w,0.f);
        c3.x=fmaxf(c3.x,0.f); c3.y=fmaxf(c3.y,0.f); c3.z=fmaxf(c3.z,0.f); c3.w=fmaxf(c3.w,0.f);
        *(float4*)(H1d + (f0+0)*ST + t0) = c0;
        *(float4*)(H1d + (f0+1)*ST + t0) = c1;
        *(float4*)(H1d + (f0+2)*ST + t0) = c2;
        *(float4*)(H1d + (f0+3)*ST + t0) = c3;
    }
    __syncthreads();

    // ---- FFN2 + residual -> head_out ----
    float* hob = g_head_out + (size_t)bid*Tn*64;
    for (int tile = tid; tile < 800; tile += 512) {
        int t0 = (tile >> 4)*4, D0 = (tile & 15)*4;
        float4 c0 = *(const float4*)(Sd + (D0+0)*ST + t0);
        float4 c1 = *(const float4*)(Sd + (D0+1)*ST + t0);
        float4 c2 = *(const float4*)(Sd + (D0+2)*ST + t0);
        float4 c3 = *(const float4*)(Sd + (D0+3)*ST + t0);
        float b0=CN[192+D0], b1=CN[192+D0+1], b2=CN[192+D0+2], b3=CN[192+D0+3];
        c0.x+=b0; c0.y+=b0; c0.z+=b0; c0.w+=b0;
        c1.x+=b1; c1.y+=b1; c1.z+=b1; c1.w+=b1;
        c2.x+=b2; c2.y+=b2; c2.z+=b2; c2.w+=b2;
        c3.x+=b3; c3.y+=b3; c3.z+=b3; c3.w+=b3;
        #pragma unroll 4
        for (int f = 0; f < 64; f++) {
            float4 hv = *(const float4*)(H1d + f*ST + t0);
            float4 wv = *(const float4*)(F2d + f*68 + D0);
            c0 = f4fma(c0, hv, wv.x); c1 = f4fma(c1, hv, wv.y);
            c2 = f4fma(c2, hv, wv.z); c3 = f4fma(c3, hv, wv.w);
        }
        *(float4*)(hob + (t0+0)*64 + D0) = make_float4(c0.x, c1.x, c2.x, c3.x);
        *(float4*)(hob + (t0+1)*64 + D0) = make_float4(c0.y, c1.y, c2.y, c3.y);
        *(float4*)(hob + (t0+2)*64 + D0) = make_float4(c0.z, c1.z, c2.z, c3.z);
        *(float4*)(hob + (t0+3)*64 + D0) = make_float4(c0.w, c1.w, c2.w, c3.w);
    }
}

// ---------------- K2: DIN MLP1 via effective-weight trick --------------------
__global__ __launch_bounds__(512)
void k_din1(const float* __restrict__ te_g, const float* __restrict__ mw1,
            const float* __restrict__ mb1) {
    extern __shared__ float sm[];
    float* HOd = sm;             // [64][ST]
    float* WBd = HOd + 64*ST;    // [64][136] d-major
    float* C0  = WBd + 64*136;   // 128
    float* TE  = C0 + 128;       // 64
    float* SS  = TE + 64;        // 128
    float* SQ  = SS + 128;       // 128

    const int bid = blockIdx.x, b = bid >> 2, h = bid & 3;
    const int tid = threadIdx.x;

    if (tid < 64)  TE[tid] = te_g[b*64 + tid];
    if (tid < 128) { SS[tid] = 0.f; SQ[tid] = 0.f; }
    __syncthreads();

    const float* hob = g_head_out + (size_t)bid*Tn*64;
    for (int o = tid; o < Tn*64; o += 512)
        HOd[(o & 63)*ST + (o >> 6)] = hob[o];

    const float* W = mw1 + (size_t)h*128*256;
    for (int o = tid; o < 128*64; o += 512) {
        int f = o >> 6, d = o & 63;
        const float* wr = W + (size_t)f*256;
        WBd[d*136 + f] = wr[64 + d] - wr[128 + d] + TE[d]*wr[192 + d];
    }
    if (tid < 128) {
        const float* wr = W + (size_t)tid*256;
        float c = mb1[h*128 + tid];
        #pragma unroll
        for (int d4 = 0; d4 < 64; d4 += 4) {
            float4 a = *(const float4*)(wr + d4);
            float4 q = *(const float4*)(wr + 128 + d4);
            c += TE[d4]*(a.x+q.x) + TE[d4+1]*(a.y+q.y)
               + TE[d4+2]*(a.z+q.z) + TE[d4+3]*(a.w+q.w);
        }
        C0[tid] = c;
    }
    __syncthreads();

    float* u1b = g_u1 + (size_t)bid*Tn*128;
    const int f0 = (tid & 31)*4;
    float sacc[4] = {0,0,0,0}, sqacc[4] = {0,0,0,0};
    float k0 = C0[f0], k1 = C0[f0+1], k2 = C0[f0+2], k3 = C0[f0+3];

    for (int tile = tid; tile < 1600; tile += 512) {     // f0 invariant mod 32
        int t0 = (tile >> 5)*4;
        float4 c0 = {k0,k0,k0,k0}, c1 = {k1,k1,k1,k1}, c2 = {k2,k2,k2,k2}, c3 = {k3,k3,k3,k3};
        #pragma unroll 4
        for (int d = 0; d < 64; d++) {
            float4 hv = *(const float4*)(HOd + d*ST + t0);
            float4 wv = *(const float4*)(WBd + d*136 + f0);
            c0 = f4fma(c0, hv, wv.x); c1 = f4fma(c1, hv, wv.y);
            c2 = f4fma(c2, hv, wv.z); c3 = f4fma(c3, hv, wv.w);
        }
        sacc[0] += c0.x+c0.y+c0.z+c0.w;  sqacc[0] += c0.x*c0.x+c0.y*c0.y+c0.z*c0.z+c0.w*c0.w;
        sacc[1] += c1.x+c1.y+c1.z+c1.w;  sqacc[1] += c1.x*c1.x+c1.y*c1.y+c1.z*c1.z+c1.w*c1.w;
        sacc[2] += c2.x+c2.y+c2.z+c2.w;  sqacc[2] += c2.x*c2.x+c2.y*c2.y+c2.z*c2.z+c2.w*c2.w;
        sacc[3] += c3.x+c3.y+c3.z+c3.w;  sqacc[3] += c3.x*c3.x+c3.y*c3.y+c3.z*c3.z+c3.w*c3.w;
        *(float4*)(u1b + (t0+0)*128 + f0) = make_float4(c0.x, c1.x, c2.x, c3.x);
        *(float4*)(u1b + (t0+1)*128 + f0) = make_float4(c0.y, c1.y, c2.y, c3.y);
        *(float4*)(u1b + (t0+2)*128 + f0) = make_float4(c0.z, c1.z, c2.z, c3.z);
        *(float4*)(u1b + (t0+3)*128 + f0) = make_float4(c0.w, c1.w, c2.w, c3.w);
    }
    #pragma unroll
    for (int i = 0; i < 4; i++) {
        atomicAdd(&SS[f0+i], sacc[i]);
        atomicAdd(&SQ[f0+i], sqacc[i]);
    }
    __syncthreads();
    if (tid < 128) {
        atomicAdd(&g_sum1[h*128 + tid], SS[tid]);
        atomicAdd(&g_sq1[h*128 + tid],  SQ[tid]);
    }
}

__global__ void k_fin1() {
    int i = threadIdx.x;
    if (i < 512) {
        float m = g_sum1[i] * (1.f/NBT);
        float v = g_sq1[i] * (1.f/NBT) - m*m;
        g_mean1[i] = m;
        g_istd1[i] = rsqrtf(v + 1e-9f);
    }
}

// ---------------- K3: dice(u1) @ mw2^T -> u2, stats2 -------------------------
__global__ __launch_bounds__(512)
void k_din2(const float* __restrict__ mw2, const float* __restrict__ mb2,
            const float* __restrict__ alpha1) {
    extern __shared__ float sm[];
    float* X1 = sm;              // [128][XT] d-major
    float* W2 = X1 + 128*XT;     // [128][68] d-major
    float* MN = W2 + 128*68;     // 128
    float* IS = MN + 128;
    float* AL = IS + 128;
    float* C0 = AL + 128;        // 64
    float* SS = C0 + 64;         // 64
    float* SQ = SS + 64;         // 64

    const int bid = blockIdx.x, h = bid & 3;
    const int tid = threadIdx.x;

    if (tid < 128) {
        MN[tid] = g_mean1[h*128 + tid];
        IS[tid] = g_istd1[h*128 + tid];
        AL[tid] = alpha1[h*128 + tid];
    }
    if (tid < 64) { C0[tid] = mb2[h*64 + tid]; SS[tid] = 0.f; SQ[tid] = 0.f; }
    for (int o = tid; o < 64*128; o += 512) {
        int g = o >> 7, d = o & 127;
        W2[d*68 + g] = mw2[(size_t)h*64*128 + o];
    }
    __syncthreads();

    const float* u1b = g_u1 + (size_t)bid*Tn*128;
    for (int o = tid; o < Tn*128; o += 512) {
        int t = o >> 7, f = o & 127;
        float x = u1b[o];
        float z = (x - MN[f]) * IS[f];
        float p = 1.f / (1.f + __expf(-z));
        X1[f*XT + t] = (p + AL[f]*(1.f - p)) * x;
    }
    __syncthreads();

    float* u2b = g_u2 + (size_t)bid*Tn*64;
    const int g0 = (tid & 15)*4;
    float sacc[4] = {0,0,0,0}, sqacc[4] = {0,0,0,0};
    float k0 = C0[g0], k1 = C0[g0+1], k2 = C0[g0+2], k3 = C0[g0+3];

    for (int tile = tid; tile < 800; tile += 512) {      // g0 invariant mod 16
        int t0 = (tile >> 4)*4;
        float4 c0 = {k0,k0,k0,k0}, c1 = {k1,k1,k1,k1}, c2 = {k2,k2,k2,k2}, c3 = {k3,k3,k3,k3};
        #pragma unroll 4
        for (int d = 0; d < 128; d++) {
            float4 hv = *(const float4*)(X1 + d*XT + t0);
            float4 wv = *(const float4*)(W2 + d*68 + g0);
            c0 = f4fma(c0, hv, wv.x); c1 = f4fma(c1, hv, wv.y);
            c2 = f4fma(c2, hv, wv.z); c3 = f4fma(c3, hv, wv.w);
        }
        sacc[0] += c0.x+c0.y+c0.z+c0.w;  sqacc[0] += c0.x*c0.x+c0.y*c0.y+c0.z*c0.z+c0.w*c0.w;
        sacc[1] += c1.x+c1.y+c1.z+c1.w;  sqacc[1] += c1.x*c1.x+c1.y*c1.y+c1.z*c1.z+c1.w*c1.w;
        sacc[2] += c2.x+c2.y+c2.z+c2.w;  sqacc[2] += c2.x*c2.x+c2.y*c2.y+c2.z*c2.z+c2.w*c2.w;
        sacc[3] += c3.x+c3.y+c3.z+c3.w;  sqacc[3] += c3.x*c3.x+c3.y*c3.y+c3.z*c3.z+c3.w*c3.w;
        *(float4*)(u2b + (t0+0)*64 + g0) = make_float4(c0.x, c1.x, c2.x, c3.x);
        *(float4*)(u2b + (t0+1)*64 + g0) = make_float4(c0.y, c1.y, c2.y, c3.y);
        *(float4*)(u2b + (t0+2)*64 + g0) = make_float4(c0.z, c1.z, c2.z, c3.z);
        *(float4*)(u2b + (t0+3)*64 + g0) = make_float4(c0.w, c1.w, c2.w, c3.w);
    }
    #pragma unroll
    for (int i = 0; i < 4; i++) {
        atomicAdd(&SS[g0+i], sacc[i]);
        atomicAdd(&SQ[g0+i], sqacc[i]);
    }
    __syncthreads();
    if (tid < 64) {
        atomicAdd(&g_sum2[h*64 + tid], SS[tid]);
        atomicAdd(&g_sq2[h*64 + tid],  SQ[tid]);
    }
}

__global__ void k_fin2() {
    int i = threadIdx.x;
    if (i < 256) {
        float m = g_sum2[i] * (1.f/NBT);
        float v = g_sq2[i] * (1.f/NBT) - m*m;
        g_mean2[i] = m;
        g_istd2[i] = rsqrtf(v + 1e-9f);
    }
}

// ---------------- K4: dice(u2) -> score -> softmax -> interests --------------
__global__ __launch_bounds__(256)
void k_final(const int* __restrict__ pad, const float* __restrict__ alpha2,
             const float* __restrict__ mw3, const float* __restrict__ mb3,
             float* __restrict__ out) {
    extern __shared__ float sm[];
    float* U2 = sm;              // [200][65]
    float* HO = U2 + 200*65;     // [200][65]
    float* SC = HO + 200*65;     // 256
    float* RD = SC + 256;        // 256
    float* MN = RD + 256;        // 64
    float* IS = MN + 64;
    float* AL = IS + 64;
    float* W3 = AL + 64;
    float* PT = W3 + 64;         // 256

    const int bid = blockIdx.x, b = bid >> 2, h = bid & 3;
    const int tid = threadIdx.x;

    if (tid < 64) {
        MN[tid] = g_mean2[h*64 + tid];
        IS[tid] = g_istd2[h*64 + tid];
        AL[tid] = alpha2[h*64 + tid];
        W3[tid] = mw3[h*64 + tid];
    }
    const float* u2b = g_u2 + (size_t)bid*Tn*64;
    const float* hob = g_head_out + (size_t)bid*Tn*64;
    for (int o = tid; o < Tn*64; o += 256) {
        int t = o >> 6, d = o & 63;
        U2[t*65 + d] = u2b[o];
        HO[t*65 + d] = hob[o];
    }
    __syncthreads();

    float v = -1e30f;
    if (tid < Tn) {
        float s = mb3[h];
        #pragma unroll 4
        for (int f = 0; f < 64; f++) {
            float x = U2[tid*65 + f];
            float z = (x - MN[f]) * IS[f];
            float p = 1.f / (1.f + __expf(-z));
            s += (p + AL[f]*(1.f - p)) * x * W3[f];
        }
        if (pad[b*Tn + tid] == 0) s = -1e9f;
        v = s;
    }
    SC[tid] = v;
    RD[tid] = v;
    __syncthreads();
    for (int s2 = 128; s2 >= 1; s2 >>= 1) {
        if (tid < s2) RD[tid] = fmaxf(RD[tid], RD[tid + s2]);
        __syncthreads();
    }
    float mx = RD[0];
    __syncthreads();
    float p = (tid < Tn) ? __expf(SC[tid] - mx) : 0.f;
    SC[tid] = p;
    RD[tid] = p;
    __syncthreads();
    for (int s2 = 128; s2 >= 1; s2 >>= 1) {
        if (tid < s2) RD[tid] += RD[tid + s2];
        __syncthreads();
    }
    float inv = 1.f / RD[0];

    const int d = tid & 63, seg = tid >> 6;
    float acc = 0.f;
    #pragma unroll 2
    for (int t = seg*50; t < seg*50 + 50; t++)
        acc += SC[t] * HO[t*65 + d];
    PT[seg*64 + d] = acc;
    __syncthreads();
    if (tid < 64)
        out[(size_t)bid*64 + tid] =
            (PT[tid] + PT[64 + tid] + PT[128 + tid] + PT[192 + tid]) * inv;
}

// ---------------- launch -----------------------------------------------------
extern "C" void kernel_launch(void* const* d_in, const int* in_sizes, int n_in,
                              void* d_out, int out_size) {
    const float* seq  = (const float*)d_in[0];
    const float* te   = (const float*)d_in[1];
    const int*   pad  = (const int*)  d_in[2];
    const float* Wqkv = (const float*)d_in[3];
    const float* Wo   = (const float*)d_in[4];
    const float* lng  = (const float*)d_in[5];
    const float* lnb  = (const float*)d_in[6];
    const float* fw1  = (const float*)d_in[7];
    const float* fb1  = (const float*)d_in[8];
    const float* fw2  = (const float*)d_in[9];
    const float* fb2  = (const float*)d_in[10];
    const float* mw1  = (const float*)d_in[11];
    const float* mb1  = (const float*)d_in[12];
    const float* al1  = (const float*)d_in[13];
    const float* mw2  = (const float*)d_in[14];
    const float* mb2  = (const float*)d_in[15];
    const float* al2  = (const float*)d_in[16];
    const float* mw3  = (const float*)d_in[17];
    const float* mb3  = (const float*)d_in[18];
    float* out = (float*)d_out;

    const size_t sm1 = (size_t)(2*64*ST + 3*16*ST + 200*17 + 64*52
                                + 16*68 + 2*64*68 + 256) * sizeof(float);
    const size_t sm2 = (size_t)(64*ST + 64*136 + 128 + 64 + 256) * sizeof(float);
    const size_t sm3 = (size_t)(128*XT + 128*68 + 3*128 + 3*64) * sizeof(float);
    const size_t sm4 = (size_t)(2*200*65 + 2*256 + 4*64 + 256) * sizeof(float);

    cudaFuncSetAttribute(k_attn_ffn, cudaFuncAttributeMaxDynamicSharedMemorySize, (int)sm1);
    cudaFuncSetAttribute(k_din1,     cudaFuncAttributeMaxDynamicSharedMemorySize, (int)sm2);
    cudaFuncSetAttribute(k_din2,     cudaFuncAttributeMaxDynamicSharedMemorySize, (int)sm3);
    cudaFuncSetAttribute(k_final,    cudaFuncAttributeMaxDynamicSharedMemorySize, (int)sm4);

    const int grid = Bx * Hn;
    k_zero<<<1, 512>>>();
    k_attn_ffn<<<grid, 512, sm1>>>(seq, Wqkv, Wo, lng, lnb, fw1, fb1, fw2, fb2);
    k_din1<<<grid, 512, sm2>>>(te, mw1, mb1);
    k_fin1<<<1, 512>>>();
    k_din2<<<grid, 512, sm3>>>(mw2, mb2, al1);
    k_fin2<<<1, 256>>>();
    k_final<<<grid, 256, sm4>>>(pad, al2, mw3, mb3, out);
}